// round 9
// baseline (speedup 1.0000x reference)
#include <cuda_runtime.h>
#include <cuda_bf16.h>

#define NN 10000
#define RP 16
#define EE 64
#define NTT 8000
#define RR 8000
#define CC 16
#define NREL 50

// packed fp32x2 FMA (Blackwell): d = a*b + d on two packed floats
#define FMA_F32X2(acc, a2, b2) \
    asm("fma.rn.f32x2 %0, %1, %2, %0;" : "+l"(acc) : "l"(a2), "l"(b2))
#define BCAST_F32X2(out, a) \
    asm("mov.b64 %0, {%1, %1};" : "=l"(out) : "r"(__float_as_uint(a)))

// ---- static scratch (no allocations) ----
__device__ float g_T1[NREL * RP];
__device__ float g_T2[NREL * RP];
__device__ int   g_p[NTT];
__device__ float g_colsum[NN * RP];
__device__ float g_rowsum[NN * RP];
__device__ float g_h[NN * EE];
__device__ float g_P[NN * RP * CC];   // P[n][r2*16+c]

// K0: zero sums/h, init out = bias2; blocks 0..49 also build latent tables.
__global__ void k_zero(const float* __restrict__ bias2, float* __restrict__ out,
                       const float* __restrict__ w1a, const float* __restrict__ b1a,
                       const float* __restrict__ w1b, const float* __restrict__ b1b,
                       const float* __restrict__ w2a, const float* __restrict__ b2a,
                       const float* __restrict__ w2b, const float* __restrict__ b2b) {
    int i = blockIdx.x * blockDim.x + threadIdx.x;
    if (i < NN * RP) { g_colsum[i] = 0.f; g_rowsum[i] = 0.f; }
    if (i < NN * EE) g_h[i] = 0.f;
    if (i < NN * CC) out[i] = bias2[i & (CC - 1)];

    if (blockIdx.x < NREL && threadIdx.x < 32) {
        int p = blockIdx.x;
        int lane = threadIdx.x;
        float a0 = fmaxf(w1a[p * EE + lane] + b1a[lane], 0.f);
        float a1 = fmaxf(w1a[p * EE + 32 + lane] + b1a[32 + lane], 0.f);
        float c0 = fmaxf(w2a[p * EE + lane] + b2a[lane], 0.f);
        float c1 = fmaxf(w2a[p * EE + 32 + lane] + b2a[32 + lane], 0.f);
        float y1[RP], y2[RP];
#pragma unroll
        for (int r = 0; r < RP; r++) {
            y1[r] = a0 * w1b[lane * RP + r] + a1 * w1b[(lane + 32) * RP + r];
            y2[r] = c0 * w2b[lane * RP + r] + c1 * w2b[(lane + 32) * RP + r];
        }
#pragma unroll
        for (int off = 16; off >= 1; off >>= 1) {
#pragma unroll
            for (int r = 0; r < RP; r++) {
                y1[r] += __shfl_xor_sync(0xffffffffu, y1[r], off);
                y2[r] += __shfl_xor_sync(0xffffffffu, y2[r], off);
            }
        }
        float m1 = -1e30f, m2 = -1e30f;
#pragma unroll
        for (int r = 0; r < RP; r++) {
            y1[r] += b1b[r]; y2[r] += b2b[r];
            m1 = fmaxf(m1, y1[r]); m2 = fmaxf(m2, y2[r]);
        }
        float s1 = 0.f, s2 = 0.f, e1 = 0.f, e2 = 0.f;
#pragma unroll
        for (int r = 0; r < RP; r++) {
            float t1 = __expf(y1[r] - m1), t2 = __expf(y2[r] - m2);
            s1 += t1; s2 += t2;
            if (lane == r) { e1 = t1; e2 = t2; }
        }
        if (lane < RP) {
            g_T1[p * RP + lane] = e1 / s1;
            g_T2[p * RP + lane] = e2 / s2;
        }
    }
}

// K2: find p[t] (float4 scan of first 50 cols); accumulate colsum/rowsum.
__global__ void k_sums(const float* __restrict__ nhots, const int* __restrict__ hind) {
    int t = blockIdx.x * blockDim.x + threadIdx.x;
    float c0 = 0.f, r0 = 0.f;
    if (t < NTT) {
        const float4* row4 = (const float4*)(nhots + (size_t)t * RR);
        int p = 0;
#pragma unroll
        for (int j = 0; j < 12; j++) {
            float4 v = row4[j];
            if (v.x != 0.f) p = 4 * j;
            if (v.y != 0.f) p = 4 * j + 1;
            if (v.z != 0.f) p = 4 * j + 2;
            if (v.w != 0.f) p = 4 * j + 3;
        }
        {
            float4 v = row4[12];
            if (v.x != 0.f) p = 48;
            if (v.y != 0.f) p = 49;
        }
        g_p[t] = p;
        int s = hind[2 * (NTT + t)];
        int o = hind[2 * (NTT + t) + 1];
#pragma unroll
        for (int r = 0; r < RP; r++) {
            float l1 = g_T1[p * RP + r], l2 = g_T2[p * RP + r];
            int ic = o * r, ir = s * r;
            if (ic) atomicAdd(&g_colsum[ic], l1); else c0 += l1;
            if (ir) atomicAdd(&g_rowsum[ir], l2); else r0 += l2;
        }
    }
#pragma unroll
    for (int off = 16; off >= 1; off >>= 1) {
        c0 += __shfl_xor_sync(0xffffffffu, c0, off);
        r0 += __shfl_xor_sync(0xffffffffu, r0, off);
    }
    if ((threadIdx.x & 31) == 0) {
        if (c0 != 0.f) atomicAdd(&g_colsum[0], c0);
        if (r0 != 0.f) atomicAdd(&g_rowsum[0], r0);
    }
}

// K3: h[s] += (L1/colsum)*weights1_flat[o*r]. Warp per t; half-warp per r parity,
// float4 lanes -> 8 fully-unrolled iterations, 8 LDG.128 in flight per lane.
__global__ void k_hacc(const int* __restrict__ hind, const float* __restrict__ w1) {
    __shared__ float sT1[NREL * RP];
    for (int i = threadIdx.x; i < NREL * RP; i += blockDim.x) sT1[i] = g_T1[i];
    __syncthreads();
    int warp = threadIdx.x >> 5, lane = threadIdx.x & 31;
    int t = blockIdx.x * 8 + warp;
    int half = lane >> 4;
    int q = lane & 15;
    int p = g_p[t];
    int s = hind[2 * (NTT + t)];
    int o = hind[2 * (NTT + t) + 1];
    float ax = 0.f, ay = 0.f, az = 0.f, aw = 0.f;
#pragma unroll
    for (int i = 0; i < 8; i++) {
        int r = 2 * i + half;
        int idx = o * r;
        float w = __fdividef(sT1[p * RP + r], g_colsum[idx]);
        float4 v = ((const float4*)(w1 + (size_t)idx * EE))[q];
        ax += w * v.x; ay += w * v.y; az += w * v.z; aw += w * v.w;
    }
    ax += __shfl_xor_sync(0xffffffffu, ax, 16);
    ay += __shfl_xor_sync(0xffffffffu, ay, 16);
    az += __shfl_xor_sync(0xffffffffu, az, 16);
    aw += __shfl_xor_sync(0xffffffffu, aw, 16);
    if (half == 0) {
        float* dst = &g_h[s * EE + q * 4];
        atomicAdd(dst + 0, ax);
        atomicAdd(dst + 1, ay);
        atomicAdd(dst + 2, az);
        atomicAdd(dst + 3, aw);
    }
}

// K5: P = relu(h+bias1)(10000x64) @ B(64x256); B[k][r2*16+c] = weights2[r2,k,c]
// Tile 64 rows x 128 cols, 256 threads, per-thread 4x8 via packed f32x2 FMA.
union PackU { unsigned long long u; float2 f; };

__global__ __launch_bounds__(256) void k_gemm(const float* __restrict__ w2,
                                              const float* __restrict__ bias1) {
    __shared__ float sA[64][68];    // [row][k], stride 68 (16B-aligned rows)
    __shared__ float sB[64][128];   // [k][col]
    int tid = threadIdx.x;
    int rb = blockIdx.x, cb = blockIdx.y;

    // load A tile: 64 rows x 64 k, float4 along k, bias+relu fused
    for (int idx4 = tid; idx4 < 64 * 16; idx4 += 256) {
        int r = idx4 >> 4;
        int k4 = (idx4 & 15) * 4;
        int gr = rb * 64 + r;
        float4 hv = make_float4(0.f, 0.f, 0.f, 0.f);
        if (gr < NN) {
            float4 h4 = *(const float4*)&g_h[gr * 64 + k4];
            float4 b4 = *(const float4*)&bias1[k4];
            hv.x = fmaxf(h4.x + b4.x, 0.f);
            hv.y = fmaxf(h4.y + b4.y, 0.f);
            hv.z = fmaxf(h4.z + b4.z, 0.f);
            hv.w = fmaxf(h4.w + b4.w, 0.f);
        }
        *(float4*)&sA[r][k4] = hv;
    }
    // load B tile: 64 k x 128 cols; col = cb*128 + j; B[k][col] = w2[(r2*64+k)*16 + c]
    for (int idx4 = tid; idx4 < 64 * 32; idx4 += 256) {
        int k = idx4 >> 5;
        int j4 = (idx4 & 31) * 4;
        int col = cb * 128 + j4;
        int r2 = col >> 4, c = col & 15;
        float4 bv = *(const float4*)&w2[((size_t)r2 * 64 + k) * 16 + c];
        *(float4*)&sB[k][j4] = bv;
    }
    __syncthreads();

    int tx = tid & 15, ty = tid >> 4;   // tx: col group of 8, ty: row group of 4
    PackU acc[4][4];
#pragma unroll
    for (int i = 0; i < 4; i++)
#pragma unroll
        for (int j = 0; j < 4; j++) acc[i][j].u = 0ull;

#pragma unroll 4
    for (int k = 0; k < 64; k++) {
        unsigned long long a2[4];
#pragma unroll
        for (int i = 0; i < 4; i++) {
            float a = sA[ty * 4 + i][k];
            BCAST_F32X2(a2[i], a);
        }
        float4 b0 = *(const float4*)&sB[k][tx * 8];
        float4 b1 = *(const float4*)&sB[k][tx * 8 + 4];
        unsigned long long bp[4];
        bp[0] = *(const unsigned long long*)&b0.x;
        bp[1] = *(const unsigned long long*)&b0.z;
        bp[2] = *(const unsigned long long*)&b1.x;
        bp[3] = *(const unsigned long long*)&b1.z;
#pragma unroll
        for (int i = 0; i < 4; i++)
#pragma unroll
            for (int j = 0; j < 4; j++)
                FMA_F32X2(acc[i][j].u, a2[i], bp[j]);
    }

#pragma unroll
    for (int i = 0; i < 4; i++) {
        int gr = rb * 64 + ty * 4 + i;
        if (gr < NN) {
            float* dst = &g_P[(size_t)gr * 256 + cb * 128 + tx * 8];
            *(float4*)dst = make_float4(acc[i][0].f.x, acc[i][0].f.y,
                                        acc[i][1].f.x, acc[i][1].f.y);
            *(float4*)(dst + 4) = make_float4(acc[i][2].f.x, acc[i][2].f.y,
                                              acc[i][3].f.x, acc[i][3].f.y);
        }
    }
}

// K6: out[np,c] += (L2/rowsum)*P[o,r2,c]. 16 lanes (c) per t, 16 t per block.
__global__ void k_scatter(const int* __restrict__ hind, float* __restrict__ out) {
    __shared__ float sT2[NREL * RP];
    __shared__ float red[256];
    for (int i = threadIdx.x; i < NREL * RP; i += 256) sT2[i] = g_T2[i];
    __syncthreads();
    int tid = threadIdx.x;
    int tt = tid >> 4, c = tid & 15;
    int half = tt & 1;
    int t = blockIdx.x * 16 + tt;
    int p = g_p[t];
    int s = hind[2 * (NTT + t)];
    int o = hind[2 * (NTT + t) + 1];
    float w_mine = __fdividef(sT2[p * RP + c], g_rowsum[s * c]);
    const float* Po = g_P + (size_t)o * 256;
    float pv[RP];
#pragma unroll
    for (int r2 = 0; r2 < RP; r2++) pv[r2] = Po[r2 * 16 + c];

    float acc0 = 0.f;
#pragma unroll
    for (int r = 0; r < RP; r++) {
        float w = __shfl_sync(0xffffffffu, w_mine, half * 16 + r);
        int flat = s * r;
        int r2 = flat / NN;
        int np = flat - r2 * NN;
        float val = w * pv[r2];
        if (flat == 0) acc0 += val;
        else atomicAdd(&out[np * CC + c], val);
    }
    red[tid] = acc0;
    __syncthreads();
    if (tt == 0) {
        float ssum = 0.f;
#pragma unroll
        for (int i = 0; i < 16; i++) ssum += red[i * 16 + c];
        atomicAdd(&out[c], ssum);
    }
}

extern "C" void kernel_launch(void* const* d_in, const int* in_sizes, int n_in,
                              void* d_out, int out_size) {
    const float* nhots = (const float*)d_in[0];
    const float* w1a = (const float*)d_in[1];
    const float* b1a = (const float*)d_in[2];
    const float* w1b = (const float*)d_in[3];
    const float* b1b = (const float*)d_in[4];
    const float* w2a = (const float*)d_in[5];
    const float* b2a = (const float*)d_in[6];
    const float* w2b = (const float*)d_in[7];
    const float* b2b = (const float*)d_in[8];
    const float* weights1 = (const float*)d_in[9];
    const float* bias1 = (const float*)d_in[10];
    const float* weights2 = (const float*)d_in[11];
    const float* bias2 = (const float*)d_in[12];
    const int* hind = (const int*)d_in[13];
    float* out = (float*)d_out;

    k_zero<<<(NN * EE + 255) / 256, 256>>>(bias2, out, w1a, b1a, w1b, b1b,
                                           w2a, b2a, w2b, b2b);
    k_sums<<<(NTT + 255) / 256, 256>>>(nhots, hind);
    k_hacc<<<NTT / 8, 256>>>(hind, weights1);
    dim3 gg((NN + 63) / 64, 2);
    k_gemm<<<gg, 256>>>(weights2, bias1);
    k_scatter<<<NTT / 16, 256>>>(hind, out);
}

// round 10
// speedup vs baseline: 1.1309x; 1.1309x over previous
#include <cuda_runtime.h>
#include <cuda_bf16.h>

#define NN 10000
#define RP 16
#define EE 64
#define NTT 8000
#define RR 8000
#define CC 16
#define NREL 50

// packed fp32x2 FMA (Blackwell): d = a*b + d on two packed floats
#define FMA_F32X2(acc, a2, b2) \
    asm("fma.rn.f32x2 %0, %1, %2, %0;" : "+l"(acc) : "l"(a2), "l"(b2))

// ---- static scratch (no allocations) ----
__device__ float g_T1[NREL * RP];
__device__ float g_T2[NREL * RP];
__device__ int   g_p[NTT];
__device__ float g_colsum[NN * RP];
__device__ float g_rowsum[NN * RP];
__device__ float g_h[NN * EE];
__device__ float g_P[NN * RP * CC];   // P[n][r2*16+c]

// K0: zero sums/h, init out = bias2; blocks 0..49 also build latent tables.
__global__ void k_zero(const float* __restrict__ bias2, float* __restrict__ out,
                       const float* __restrict__ w1a, const float* __restrict__ b1a,
                       const float* __restrict__ w1b, const float* __restrict__ b1b,
                       const float* __restrict__ w2a, const float* __restrict__ b2a,
                       const float* __restrict__ w2b, const float* __restrict__ b2b) {
    int i = blockIdx.x * blockDim.x + threadIdx.x;
    if (i < NN * RP) { g_colsum[i] = 0.f; g_rowsum[i] = 0.f; }
    if (i < NN * EE) g_h[i] = 0.f;
    if (i < NN * CC) out[i] = bias2[i & (CC - 1)];

    if (blockIdx.x < NREL && threadIdx.x < 32) {
        int p = blockIdx.x;
        int lane = threadIdx.x;
        float a0 = fmaxf(w1a[p * EE + lane] + b1a[lane], 0.f);
        float a1 = fmaxf(w1a[p * EE + 32 + lane] + b1a[32 + lane], 0.f);
        float c0 = fmaxf(w2a[p * EE + lane] + b2a[lane], 0.f);
        float c1 = fmaxf(w2a[p * EE + 32 + lane] + b2a[32 + lane], 0.f);
        float y1[RP], y2[RP];
#pragma unroll
        for (int r = 0; r < RP; r++) {
            y1[r] = a0 * w1b[lane * RP + r] + a1 * w1b[(lane + 32) * RP + r];
            y2[r] = c0 * w2b[lane * RP + r] + c1 * w2b[(lane + 32) * RP + r];
        }
#pragma unroll
        for (int off = 16; off >= 1; off >>= 1) {
#pragma unroll
            for (int r = 0; r < RP; r++) {
                y1[r] += __shfl_xor_sync(0xffffffffu, y1[r], off);
                y2[r] += __shfl_xor_sync(0xffffffffu, y2[r], off);
            }
        }
        float m1 = -1e30f, m2 = -1e30f;
#pragma unroll
        for (int r = 0; r < RP; r++) {
            y1[r] += b1b[r]; y2[r] += b2b[r];
            m1 = fmaxf(m1, y1[r]); m2 = fmaxf(m2, y2[r]);
        }
        float s1 = 0.f, s2 = 0.f, e1 = 0.f, e2 = 0.f;
#pragma unroll
        for (int r = 0; r < RP; r++) {
            float t1 = __expf(y1[r] - m1), t2 = __expf(y2[r] - m2);
            s1 += t1; s2 += t2;
            if (lane == r) { e1 = t1; e2 = t2; }
        }
        if (lane < RP) {
            g_T1[p * RP + lane] = e1 / s1;
            g_T2[p * RP + lane] = e2 / s2;
        }
    }
}

// K2: find p[t] (float4 scan of first 50 cols); accumulate colsum/rowsum.
__global__ void k_sums(const float* __restrict__ nhots, const int* __restrict__ hind) {
    int t = blockIdx.x * blockDim.x + threadIdx.x;
    float c0 = 0.f, r0 = 0.f;
    if (t < NTT) {
        const float4* row4 = (const float4*)(nhots + (size_t)t * RR);
        int p = 0;
#pragma unroll
        for (int j = 0; j < 12; j++) {
            float4 v = row4[j];
            if (v.x != 0.f) p = 4 * j;
            if (v.y != 0.f) p = 4 * j + 1;
            if (v.z != 0.f) p = 4 * j + 2;
            if (v.w != 0.f) p = 4 * j + 3;
        }
        {
            float4 v = row4[12];
            if (v.x != 0.f) p = 48;
            if (v.y != 0.f) p = 49;
        }
        g_p[t] = p;
        int s = hind[2 * (NTT + t)];
        int o = hind[2 * (NTT + t) + 1];
#pragma unroll
        for (int r = 0; r < RP; r++) {
            float l1 = g_T1[p * RP + r], l2 = g_T2[p * RP + r];
            int ic = o * r, ir = s * r;
            if (ic) atomicAdd(&g_colsum[ic], l1); else c0 += l1;
            if (ir) atomicAdd(&g_rowsum[ir], l2); else r0 += l2;
        }
    }
#pragma unroll
    for (int off = 16; off >= 1; off >>= 1) {
        c0 += __shfl_xor_sync(0xffffffffu, c0, off);
        r0 += __shfl_xor_sync(0xffffffffu, r0, off);
    }
    if ((threadIdx.x & 31) == 0) {
        if (c0 != 0.f) atomicAdd(&g_colsum[0], c0);
        if (r0 != 0.f) atomicAdd(&g_rowsum[0], r0);
    }
}

// K3: h[s] += (L1/colsum)*weights1_flat[o*r]. Warp per t; half-warp per r parity,
// float4 lanes -> 8 fully-unrolled iterations, 8 LDG.128 in flight per lane.
__global__ void k_hacc(const int* __restrict__ hind, const float* __restrict__ w1) {
    __shared__ float sT1[NREL * RP];
    for (int i = threadIdx.x; i < NREL * RP; i += blockDim.x) sT1[i] = g_T1[i];
    __syncthreads();
    int warp = threadIdx.x >> 5, lane = threadIdx.x & 31;
    int t = blockIdx.x * 8 + warp;
    int half = lane >> 4;
    int q = lane & 15;
    int p = g_p[t];
    int s = hind[2 * (NTT + t)];
    int o = hind[2 * (NTT + t) + 1];
    float ax = 0.f, ay = 0.f, az = 0.f, aw = 0.f;
#pragma unroll
    for (int i = 0; i < 8; i++) {
        int r = 2 * i + half;
        int idx = o * r;
        float w = __fdividef(sT1[p * RP + r], g_colsum[idx]);
        float4 v = ((const float4*)(w1 + (size_t)idx * EE))[q];
        ax += w * v.x; ay += w * v.y; az += w * v.z; aw += w * v.w;
    }
    ax += __shfl_xor_sync(0xffffffffu, ax, 16);
    ay += __shfl_xor_sync(0xffffffffu, ay, 16);
    az += __shfl_xor_sync(0xffffffffu, az, 16);
    aw += __shfl_xor_sync(0xffffffffu, aw, 16);
    if (half == 0) {
        float* dst = &g_h[s * EE + q * 4];
        atomicAdd(dst + 0, ax);
        atomicAdd(dst + 1, ay);
        atomicAdd(dst + 2, az);
        atomicAdd(dst + 3, aw);
    }
}

// K5: P = relu(h+bias1)(10000x64) @ B(64x256); B[k][r2*16+c] = weights2[r2,k,c]
// Tile 64x64, 256 threads, per-thread 4 rows x 4 cols (cols tx, tx+16, tx+32, tx+48).
// f32x2 packed along K: acc2 += (a[2k],a[2k+1]) * (b[2k],b[2k+1]); horizontal add at end.
// sA row-major pad 68 (a-loads broadcast); sBT transposed pad 66 (b-loads conflict-free).
union PackU { unsigned long long u; float2 f; };

__global__ __launch_bounds__(256) void k_gemm(const float* __restrict__ w2,
                                              const float* __restrict__ bias1) {
    __shared__ float sA[64][68];    // [row][k]
    __shared__ float sBT[64][66];   // [colLocal][k]
    int tid = threadIdx.x;
    int rb = blockIdx.x, cb = blockIdx.y;

    // A tile: 64 rows x 64 k, float4 along k, bias+relu fused
    for (int idx4 = tid; idx4 < 64 * 16; idx4 += 256) {
        int r = idx4 >> 4;
        int k4 = (idx4 & 15) * 4;
        int gr = rb * 64 + r;
        float4 hv = make_float4(0.f, 0.f, 0.f, 0.f);
        if (gr < NN) {
            float4 h4 = *(const float4*)&g_h[gr * 64 + k4];
            float4 b4 = *(const float4*)&bias1[k4];
            hv.x = fmaxf(h4.x + b4.x, 0.f);
            hv.y = fmaxf(h4.y + b4.y, 0.f);
            hv.z = fmaxf(h4.z + b4.z, 0.f);
            hv.w = fmaxf(h4.w + b4.w, 0.f);
        }
        *(float4*)&sA[r][k4] = hv;
    }
    // B tile transposed: sBT[colL][k] = B[k][cb*64+colL] = w2[(r2*64+k)*16+c]
    for (int idx4 = tid; idx4 < 64 * 16; idx4 += 256) {
        int k = idx4 >> 4;
        int colL = (idx4 & 15) * 4;
        int colG = cb * 64 + colL;
        int r2 = colG >> 4, c = colG & 15;
        float4 bv = *(const float4*)&w2[((size_t)r2 * 64 + k) * 16 + c];
        sBT[colL + 0][k] = bv.x;
        sBT[colL + 1][k] = bv.y;
        sBT[colL + 2][k] = bv.z;
        sBT[colL + 3][k] = bv.w;
    }
    __syncthreads();

    int tx = tid & 15, ty = tid >> 4;
    PackU acc[4][4];
#pragma unroll
    for (int i = 0; i < 4; i++)
#pragma unroll
        for (int j = 0; j < 4; j++) acc[i][j].u = 0ull;

#pragma unroll 4
    for (int kh = 0; kh < 32; kh++) {
        unsigned long long a2[4], b2[4];
#pragma unroll
        for (int i = 0; i < 4; i++)
            a2[i] = *(const unsigned long long*)&sA[ty * 4 + i][2 * kh];
#pragma unroll
        for (int j = 0; j < 4; j++)
            b2[j] = *(const unsigned long long*)&sBT[tx + 16 * j][2 * kh];
#pragma unroll
        for (int i = 0; i < 4; i++)
#pragma unroll
            for (int j = 0; j < 4; j++)
                FMA_F32X2(acc[i][j].u, a2[i], b2[j]);
    }

#pragma unroll
    for (int i = 0; i < 4; i++) {
        int gr = rb * 64 + ty * 4 + i;
        if (gr < NN) {
            float* dst = &g_P[(size_t)gr * 256 + cb * 64];
#pragma unroll
            for (int j = 0; j < 4; j++)
                dst[tx + 16 * j] = acc[i][j].f.x + acc[i][j].f.y;
        }
    }
}

// K6: out[np,c] += (L2/rowsum)*P[o,r2,c]. 16 lanes (c) per t, 16 t per block.
__global__ void k_scatter(const int* __restrict__ hind, float* __restrict__ out) {
    __shared__ float sT2[NREL * RP];
    __shared__ float red[256];
    for (int i = threadIdx.x; i < NREL * RP; i += 256) sT2[i] = g_T2[i];
    __syncthreads();
    int tid = threadIdx.x;
    int tt = tid >> 4, c = tid & 15;
    int half = tt & 1;
    int t = blockIdx.x * 16 + tt;
    int p = g_p[t];
    int s = hind[2 * (NTT + t)];
    int o = hind[2 * (NTT + t) + 1];
    float w_mine = __fdividef(sT2[p * RP + c], g_rowsum[s * c]);
    const float* Po = g_P + (size_t)o * 256;
    float pv[RP];
#pragma unroll
    for (int r2 = 0; r2 < RP; r2++) pv[r2] = Po[r2 * 16 + c];

    float acc0 = 0.f;
#pragma unroll
    for (int r = 0; r < RP; r++) {
        float w = __shfl_sync(0xffffffffu, w_mine, half * 16 + r);
        int flat = s * r;
        int r2 = flat / NN;
        int np = flat - r2 * NN;
        float val = w * pv[r2];
        if (flat == 0) acc0 += val;
        else atomicAdd(&out[np * CC + c], val);
    }
    red[tid] = acc0;
    __syncthreads();
    if (tt == 0) {
        float ssum = 0.f;
#pragma unroll
        for (int i = 0; i < 16; i++) ssum += red[i * 16 + c];
        atomicAdd(&out[c], ssum);
    }
}

extern "C" void kernel_launch(void* const* d_in, const int* in_sizes, int n_in,
                              void* d_out, int out_size) {
    const float* nhots = (const float*)d_in[0];
    const float* w1a = (const float*)d_in[1];
    const float* b1a = (const float*)d_in[2];
    const float* w1b = (const float*)d_in[3];
    const float* b1b = (const float*)d_in[4];
    const float* w2a = (const float*)d_in[5];
    const float* b2a = (const float*)d_in[6];
    const float* w2b = (const float*)d_in[7];
    const float* b2b = (const float*)d_in[8];
    const float* weights1 = (const float*)d_in[9];
    const float* bias1 = (const float*)d_in[10];
    const float* weights2 = (const float*)d_in[11];
    const float* bias2 = (const float*)d_in[12];
    const int* hind = (const int*)d_in[13];
    float* out = (float*)d_out;

    k_zero<<<(NN * EE + 255) / 256, 256>>>(bias2, out, w1a, b1a, w1b, b1b,
                                           w2a, b2a, w2b, b2b);
    k_sums<<<(NTT + 255) / 256, 256>>>(nhots, hind);
    k_hacc<<<NTT / 8, 256>>>(hind, weights1);
    dim3 gg((NN + 63) / 64, 4);
    k_gemm<<<gg, 256>>>(weights2, bias1);
    k_scatter<<<NTT / 16, 256>>>(hind, out);
}